// round 9
// baseline (speedup 1.0000x reference)
#include <cuda_runtime.h>
#include <cuda_fp16.h>
#include <cstdint>
#include <math.h>

#define N_ROWS 65536
#define D      256
#define K      2048

// ---------------- device scratch ----------------
__device__ __align__(16) __half g_xh[N_ROWS][D];   // 64*x hi limb
__device__ __align__(16) __half g_xl[N_ROWS][D];   // 64*x lo limb
__device__ __align__(16) __half g_eh[K][D];        // 64*e hi limb (code-major)
__device__ __align__(16) __half g_el[K][D];        // 64*e lo limb
__device__ float g_codeT[K * D];
__device__ float g_norms[K];
__device__ int   g_counts[K];
__device__ int   g_idx[N_ROWS];
__device__ float g_partials[2048];

__device__ __forceinline__ uint32_t smem_u32(const void* p) {
    uint32_t a;
    asm("{ .reg .u64 t; cvta.to.shared.u64 t, %1; cvt.u32.u64 %0, t; }" : "=r"(a) : "l"(p));
    return a;
}
#define CP_ASYNC16(dst, src) \
    asm volatile("cp.async.cg.shared.global [%0], [%1], 16;" :: "r"(dst), "l"(src))
#define CP_COMMIT() asm volatile("cp.async.commit_group;" ::: "memory")
#define CP_WAIT(n)  asm volatile("cp.async.wait_group %0;" :: "n"(n) : "memory")
#define LDMATRIX4(r, a) \
    asm volatile("ldmatrix.sync.aligned.m8n8.x4.shared.b16 {%0,%1,%2,%3}, [%4];" \
        : "=r"((r)[0]), "=r"((r)[1]), "=r"((r)[2]), "=r"((r)[3]) : "r"(a))
#define MMA16816(c, a, b) \
    asm volatile("mma.sync.aligned.m16n8k16.row.col.f32.f16.f16.f32 " \
        "{%0,%1,%2,%3}, {%4,%5,%6,%7}, {%8,%9}, {%0,%1,%2,%3};" \
        : "+f"((c)[0]), "+f"((c)[1]), "+f"((c)[2]), "+f"((c)[3]) \
        : "r"((a)[0]), "r"((a)[1]), "r"((a)[2]), "r"((a)[3]), "r"((b)[0]), "r"((b)[1]))

// ---------------- prep kernels ----------------
__global__ void transpose_kernel(const float* __restrict__ cb) {
    __shared__ float tile[32][33];
    int k0 = blockIdx.x * 32, d0 = blockIdx.y * 32, x = threadIdx.x, y = threadIdx.y;
    #pragma unroll
    for (int i = 0; i < 32; i += 8) tile[y + i][x] = cb[(size_t)(d0 + y + i) * K + k0 + x];
    __syncthreads();
    #pragma unroll
    for (int i = 0; i < 32; i += 8) {
        int k = k0 + y + i, d = d0 + x;
        float v = tile[x][y + i];
        g_codeT[(size_t)k * D + d] = v;
        float vs = v * 64.0f;
        __half h = __float2half(vs);
        g_eh[k][d] = h;
        g_el[k][d] = __float2half(vs - __half2float(h));
    }
    if (blockIdx.y == 0 && threadIdx.y == 0) g_counts[k0 + x] = 0;
}

__global__ void norms_kernel() {
    __shared__ float s[256];
    int k = blockIdx.x, t = threadIdx.x;
    float v = g_codeT[(size_t)k * D + t];
    s[t] = v * v;
    __syncthreads();
    for (int r = 128; r > 0; r >>= 1) { if (t < r) s[t] += s[t + r]; __syncthreads(); }
    if (t == 0) g_norms[k] = s[0];
}

__global__ __launch_bounds__(256) void split_x_kernel(const float* __restrict__ X) {
    int i = blockIdx.x * 256 + threadIdx.x;
    int row = i >> 5, d0 = (i & 31) << 3;
    const float4* src = (const float4*)(X + (size_t)row * D + d0);
    float4 v0 = src[0], v1 = src[1];
    float vs[8] = {v0.x, v0.y, v0.z, v0.w, v1.x, v1.y, v1.z, v1.w};
    __align__(16) __half ph[8], pl[8];
    #pragma unroll
    for (int j = 0; j < 8; j++) {
        float v = vs[j] * 64.0f;
        __half h = __float2half(v);
        ph[j] = h;
        pl[j] = __float2half(v - __half2float(h));
    }
    *(uint4*)&g_xh[row][d0] = *(uint4*)ph;
    *(uint4*)&g_xl[row][d0] = *(uint4*)pl;
}

// ---------------- main: HMMA distance GEMM + fused argmin ----------------
// 512 threads = 16 warps: mwarp=wid&3 (32 rows), nwarp=wid>>2 (32 cols)
// K-concat: chunks kc 0-3 xh*eh, 4-7 xh*el, 8-11 xl*eh (64 halves each)
// 3-stage cp.async pipeline, 1 sync per chunk, flattened over 16 tiles x 12 chunks
#define STG 32768   // per stage: A 16KB + B 16KB

__device__ __forceinline__ void issue_chunk(uint32_t sb, int row0, int gc,
                                            const int* lrow, const int* lcolb) {
    int ct = gc / 12, kc = gc - ct * 12;
    int c0 = ct * 128, koff = (kc & 3) * 64;
    const __half* Asrc = (kc < 8) ? &g_xh[0][0] : &g_xl[0][0];
    const __half* Bsrc = (kc >= 4 && kc < 8) ? &g_el[0][0] : &g_eh[0][0];
    uint32_t st = sb + (gc % 3) * STG;
    #pragma unroll
    for (int j = 0; j < 2; j++) {
        int off = lrow[j] * 128 + lcolb[j];
        int sw = off ^ ((off >> 3) & 0x70);
        CP_ASYNC16(st + sw,
                   (const char*)(Asrc + (size_t)(row0 + lrow[j]) * D + koff) + lcolb[j]);
        CP_ASYNC16(st + 16384 + sw,
                   (const char*)(Bsrc + (size_t)(c0 + lrow[j]) * D + koff) + lcolb[j]);
    }
    CP_COMMIT();
}

__global__ __launch_bounds__(512, 1) void argmin_mma_kernel() {
    extern __shared__ char smem[];
    __shared__ unsigned long long sMin[128];
    uint32_t sb = smem_u32(smem);

    int tid = threadIdx.x, l = tid & 31, wid = tid >> 5;
    int mwarp = wid & 3, nwarp = wid >> 2;
    int row0 = blockIdx.x * 128;
    if (tid < 128) sMin[tid] = 0xFFFFFFFFFFFFFFFFULL;

    int lrow[2], lcolb[2];
    #pragma unroll
    for (int j = 0; j < 2; j++) {
        int lin = j * 512 + tid;        // 1024 x 16B per matrix
        lrow[j] = lin >> 3;
        lcolb[j] = (lin & 7) * 16;
    }

    float best[2][2];
    int   bidx[2][2];
    #pragma unroll
    for (int a = 0; a < 2; a++)
        #pragma unroll
        for (int b = 0; b < 2; b++) { best[a][b] = 3.4e38f; bidx[a][b] = 0; }

    float acc[2][4][4];

    issue_chunk(sb, row0, 0, lrow, lcolb);
    issue_chunk(sb, row0, 1, lrow, lcolb);

    for (int gc = 0; gc < 192; gc++) {
        int ct = gc / 12, kc = gc - ct * 12;
        int c0 = ct * 128;

        if (gc == 191) { CP_WAIT(0); } else { CP_WAIT(1); }
        __syncthreads();
        if (gc + 2 < 192) issue_chunk(sb, row0, gc + 2, lrow, lcolb);

        if (kc == 0) {
            #pragma unroll
            for (int mf = 0; mf < 2; mf++)
                #pragma unroll
                for (int nf = 0; nf < 4; nf++)
                    #pragma unroll
                    for (int q = 0; q < 4; q++) acc[mf][nf][q] = 0.f;
        }

        uint32_t aBase = sb + (gc % 3) * STG;
        uint32_t bBase = aBase + 16384;
        #pragma unroll
        for (int ks = 0; ks < 4; ks++) {
            uint32_t afr[2][4];
            #pragma unroll
            for (int mf = 0; mf < 2; mf++) {
                int row = mwarp * 32 + mf * 16 + (l & 15);
                int colb = ks * 32 + ((l >> 4) << 4);
                int off = row * 128 + colb;
                LDMATRIX4(afr[mf], aBase + (off ^ ((off >> 3) & 0x70)));
            }
            uint32_t bfr[4][2];
            #pragma unroll
            for (int np = 0; np < 2; np++) {
                int code = nwarp * 32 + np * 16 + (l & 7) + ((l & 16) ? 8 : 0);
                int colb = ks * 32 + ((l & 8) ? 16 : 0);
                int off = code * 128 + colb;
                uint32_t r[4];
                LDMATRIX4(r, bBase + (off ^ ((off >> 3) & 0x70)));
                bfr[np * 2][0] = r[0]; bfr[np * 2][1] = r[1];
                bfr[np * 2 + 1][0] = r[2]; bfr[np * 2 + 1][1] = r[3];
            }
            #pragma unroll
            for (int mf = 0; mf < 2; mf++)
                #pragma unroll
                for (int nf = 0; nf < 4; nf++)
                    MMA16816(acc[mf][nf], afr[mf], bfr[nf]);
        }

        if (kc == 11) {       // tile done: fused argmin epilogue (cols ascending)
            #pragma unroll
            for (int nf = 0; nf < 4; nf++) {
                int n0 = c0 + nwarp * 32 + nf * 8 + 2 * (l & 3);
                float nr0 = __ldg(&g_norms[n0]) * 4096.0f;
                float nr1 = __ldg(&g_norms[n0 + 1]) * 4096.0f;
                #pragma unroll
                for (int mf = 0; mf < 2; mf++) {
                    float d00 = fmaf(-2.0f, acc[mf][nf][0], nr0);
                    float d01 = fmaf(-2.0f, acc[mf][nf][1], nr1);
                    float d10 = fmaf(-2.0f, acc[mf][nf][2], nr0);
                    float d11 = fmaf(-2.0f, acc[mf][nf][3], nr1);
                    if (d00 < best[mf][0]) { best[mf][0] = d00; bidx[mf][0] = n0; }
                    if (d01 < best[mf][0]) { best[mf][0] = d01; bidx[mf][0] = n0 + 1; }
                    if (d10 < best[mf][1]) { best[mf][1] = d10; bidx[mf][1] = n0; }
                    if (d11 < best[mf][1]) { best[mf][1] = d11; bidx[mf][1] = n0 + 1; }
                }
            }
        }
    }

    // lane merge over the 4 column-lanes (l&3), then packed atomicMin merge
    #pragma unroll
    for (int mf = 0; mf < 2; mf++)
        #pragma unroll
        for (int rh = 0; rh < 2; rh++) {
            float bv = best[mf][rh]; int bi = bidx[mf][rh];
            #pragma unroll
            for (int dlt = 1; dlt <= 2; dlt <<= 1) {
                float ov = __shfl_xor_sync(0xFFFFFFFFu, bv, dlt);
                int   oi = __shfl_xor_sync(0xFFFFFFFFu, bi, dlt);
                if (ov < bv || (ov == bv && oi < bi)) { bv = ov; bi = oi; }
            }
            if ((l & 3) == 0) {
                int row = mwarp * 32 + mf * 16 + rh * 8 + (l >> 2);
                uint32_t b = __float_as_uint(bv);
                b = (b & 0x80000000u) ? ~b : (b | 0x80000000u);   // monotone key
                unsigned long long key = ((unsigned long long)b << 32) | (uint32_t)bi;
                atomicMin(&sMin[row], key);
            }
        }
    __syncthreads();
    if (tid < 128) {
        int bi = (int)(uint32_t)(sMin[tid] & 0xFFFFFFFFULL);
        g_idx[row0 + tid] = bi;
        atomicAdd(&g_counts[bi], 1);
    }
}

// ---------------- epilogue kernels ----------------
__global__ __launch_bounds__(256) void quantize_kernel(const float* __restrict__ X,
                                                       float* __restrict__ out) {
    const int total4 = N_ROWS * D / 4;
    int stride = gridDim.x * blockDim.x;
    float sum = 0.f;
    for (int i = blockIdx.x * blockDim.x + threadIdx.x; i < total4; i += stride) {
        int row = i >> 6, d4 = (i & 63) << 2;
        float4 xv = ((const float4*)X)[i];
        float4 q = *(const float4*)&g_codeT[(size_t)g_idx[row] * D + d4];
        ((float4*)out)[i] = q;
        float dx = xv.x - q.x, dy = xv.y - q.y, dz = xv.z - q.z, dw = xv.w - q.w;
        sum += dx * dx + dy * dy + dz * dz + dw * dw;
    }
    __shared__ float s[256];
    s[threadIdx.x] = sum;
    __syncthreads();
    for (int r = 128; r > 0; r >>= 1) { if (threadIdx.x < r) s[threadIdx.x] += s[threadIdx.x + r]; __syncthreads(); }
    if (threadIdx.x == 0) g_partials[blockIdx.x] = s[0];
}

__global__ void finalize_kernel(float* __restrict__ out) {
    __shared__ double sd[256];
    int t = threadIdx.x;
    double s = 0.0;
    for (int i = t; i < 2048; i += 256) s += (double)g_partials[i];
    sd[t] = s;
    __syncthreads();
    for (int r = 128; r > 0; r >>= 1) { if (t < r) sd[t] += sd[t + r]; __syncthreads(); }
    double loss = 1.25 * sd[0] / (double)((long long)N_ROWS * D);
    __syncthreads();
    double h = 0.0;
    for (int i = t; i < K; i += 256) {
        double p = (double)g_counts[i] / (double)N_ROWS;
        h += p * log(p + 1e-10);
    }
    sd[t] = h;
    __syncthreads();
    for (int r = 128; r > 0; r >>= 1) { if (t < r) sd[t] += sd[t + r]; __syncthreads(); }
    if (t == 0) {
        out[(size_t)N_ROWS * D]     = (float)loss;
        out[(size_t)N_ROWS * D + 1] = (float)exp(-sd[0]);
    }
}

// ------------------------------------------------------------------
extern "C" void kernel_launch(void* const* d_in, const int* in_sizes, int n_in,
                              void* d_out, int out_size) {
    const float* x  = (const float*)d_in[0];
    const float* cb = (const float*)d_in[1];
    float* out = (float*)d_out;

    cudaFuncSetAttribute(argmin_mma_kernel,
                         cudaFuncAttributeMaxDynamicSharedMemorySize, 3 * STG);

    transpose_kernel<<<dim3(K / 32, D / 32), dim3(32, 8)>>>(cb);
    norms_kernel<<<K, 256>>>();
    split_x_kernel<<<N_ROWS * D / 8 / 256, 256>>>(x);
    argmin_mma_kernel<<<N_ROWS / 128, 512, 3 * STG>>>();
    quantize_kernel<<<2048, 256>>>(x, out);
    finalize_kernel<<<1, 256>>>(out);
}

// round 10
// speedup vs baseline: 1.3245x; 1.3245x over previous
#include <cuda_runtime.h>
#include <cuda_fp16.h>
#include <cstdint>
#include <math.h>

#define N_ROWS 65536
#define D      256
#define K      2048

// ---------------- device scratch ----------------
__device__ __align__(16) __half g_xh[N_ROWS][D];   // 64*x hi limb
__device__ __align__(16) __half g_xl[N_ROWS][D];   // 64*x lo limb
__device__ __align__(16) __half g_eh[K][D];        // 64*e hi limb (code-major)
__device__ __align__(16) __half g_el[K][D];        // 64*e lo limb
__device__ float g_codeT[K * D];
__device__ float g_norms[K];
__device__ int   g_counts[K];
__device__ int   g_idx[N_ROWS];
__device__ float g_partials[2048];

__device__ __forceinline__ uint32_t smem_u32(const void* p) {
    uint32_t a;
    asm("{ .reg .u64 t; cvta.to.shared.u64 t, %1; cvt.u32.u64 %0, t; }" : "=r"(a) : "l"(p));
    return a;
}
#define CP_ASYNC16(dst, src) \
    asm volatile("cp.async.cg.shared.global [%0], [%1], 16;" :: "r"(dst), "l"(src))
#define CP_COMMIT() asm volatile("cp.async.commit_group;" ::: "memory")
#define CP_WAIT(n)  asm volatile("cp.async.wait_group %0;" :: "n"(n) : "memory")
#define LDMATRIX4(r, a) \
    asm volatile("ldmatrix.sync.aligned.m8n8.x4.shared.b16 {%0,%1,%2,%3}, [%4];" \
        : "=r"((r)[0]), "=r"((r)[1]), "=r"((r)[2]), "=r"((r)[3]) : "r"(a))
#define MMA16816(c, a, b) \
    asm volatile("mma.sync.aligned.m16n8k16.row.col.f32.f16.f16.f32 " \
        "{%0,%1,%2,%3}, {%4,%5,%6,%7}, {%8,%9}, {%0,%1,%2,%3};" \
        : "+f"((c)[0]), "+f"((c)[1]), "+f"((c)[2]), "+f"((c)[3]) \
        : "r"((a)[0]), "r"((a)[1]), "r"((a)[2]), "r"((a)[3]), "r"((b)[0]), "r"((b)[1]))

// ---------------- prep kernels ----------------
__global__ void transpose_kernel(const float* __restrict__ cb) {
    __shared__ float tile[32][33];
    int k0 = blockIdx.x * 32, d0 = blockIdx.y * 32, x = threadIdx.x, y = threadIdx.y;
    #pragma unroll
    for (int i = 0; i < 32; i += 8) tile[y + i][x] = cb[(size_t)(d0 + y + i) * K + k0 + x];
    __syncthreads();
    #pragma unroll
    for (int i = 0; i < 32; i += 8) {
        int k = k0 + y + i, d = d0 + x;
        float v = tile[x][y + i];
        g_codeT[(size_t)k * D + d] = v;
        float vs = v * 64.0f;
        __half h = __float2half(vs);
        g_eh[k][d] = h;
        g_el[k][d] = __float2half(vs - __half2float(h));
    }
    if (blockIdx.y == 0 && threadIdx.y == 0) g_counts[k0 + x] = 0;
}

__global__ void norms_kernel() {
    __shared__ float s[256];
    int k = blockIdx.x, t = threadIdx.x;
    float v = g_codeT[(size_t)k * D + t];
    s[t] = v * v;
    __syncthreads();
    for (int r = 128; r > 0; r >>= 1) { if (t < r) s[t] += s[t + r]; __syncthreads(); }
    if (t == 0) g_norms[k] = s[0];
}

__global__ __launch_bounds__(256) void split_x_kernel(const float* __restrict__ X) {
    int i = blockIdx.x * 256 + threadIdx.x;
    int row = i >> 5, d0 = (i & 31) << 3;
    const float4* src = (const float4*)(X + (size_t)row * D + d0);
    float4 v0 = src[0], v1 = src[1];
    float vs[8] = {v0.x, v0.y, v0.z, v0.w, v1.x, v1.y, v1.z, v1.w};
    __align__(16) __half ph[8], pl[8];
    #pragma unroll
    for (int j = 0; j < 8; j++) {
        float v = vs[j] * 64.0f;
        __half h = __float2half(v);
        ph[j] = h;
        pl[j] = __float2half(v - __half2float(h));
    }
    *(uint4*)&g_xh[row][d0] = *(uint4*)ph;
    *(uint4*)&g_xl[row][d0] = *(uint4*)pl;
}

// ---------------- main: HMMA distance GEMM + fused argmin ----------------
// 256 threads = 8 warps: mwarp=wid&1 (64 rows), nwarp=wid>>1 (64 cols)
// CTA tile 128 rows x 256 cols, 8 col-tiles.
// A (xh,xl: 8 slabs x 16KB = 128KB) RESIDENT in smem.
// B streamed per 64-half chunk (32KB), 3 stages. Per tile: B chunks
// eh[0..3], el[0..3]; eh chunks feed 2 passes (xh*eh, xl*eh), el feed 1 (xh*el).
#define BOFF 131072
#define BSTG 32768
#define SMEMSZ (BOFF + 3 * BSTG)   // 229376

__device__ __forceinline__ void issue_b(uint32_t sb, int gb, int tid) {
    int ct = gb >> 3, bc = gb & 7, g = bc & 3;
    const char* base = (bc < 4) ? (const char*)g_eh : (const char*)g_el;
    uint32_t st = sb + BOFF + (gb % 3) * BSTG;
    #pragma unroll
    for (int j = 0; j < 8; j++) {
        int lin = j * 256 + tid;
        int row = lin >> 3, colb = (lin & 7) * 16;
        int off = row * 128 + colb;
        CP_ASYNC16(st + (off ^ ((off >> 3) & 0x70)),
                   base + (size_t)(ct * 256 + row) * 512 + g * 128 + colb);
    }
    CP_COMMIT();
}

__global__ __launch_bounds__(256, 1) void argmin_mma_kernel() {
    extern __shared__ char smem[];
    __shared__ unsigned long long sMin[128];
    uint32_t sb = smem_u32(smem);

    int tid = threadIdx.x, l = tid & 31, wid = tid >> 5;
    int mwarp = wid & 1, nwarp = wid >> 1;
    int row0 = blockIdx.x * 128;
    if (tid < 128) sMin[tid] = 0xFFFFFFFFFFFFFFFFULL;

    // A resident: 8 slabs (xh g=0..3, xl g=0..3), 128 rows x 128B each, SW128
    #pragma unroll
    for (int s = 0; s < 8; s++) {
        const char* base = (s < 4) ? (const char*)g_xh : (const char*)g_xl;
        int g = s & 3;
        #pragma unroll
        for (int j = 0; j < 4; j++) {
            int lin = j * 256 + tid;
            int row = lin >> 3, colb = (lin & 7) * 16;
            int off = row * 128 + colb;
            CP_ASYNC16(sb + s * 16384 + (off ^ ((off >> 3) & 0x70)),
                       base + (size_t)(row0 + row) * 512 + g * 128 + colb);
        }
    }
    CP_COMMIT();
    issue_b(sb, 0, tid);
    issue_b(sb, 1, tid);

    float best[4][2];
    int   bidx[4][2];
    #pragma unroll
    for (int a = 0; a < 4; a++)
        #pragma unroll
        for (int b = 0; b < 2; b++) { best[a][b] = 3.4e38f; bidx[a][b] = 0; }

    float acc[4][8][4];

    for (int gb = 0; gb < 64; gb++) {
        int ct = gb >> 3, bc = gb & 7, c0 = ct * 256;

        if (gb == 63) { CP_WAIT(0); } else { CP_WAIT(1); }
        __syncthreads();
        if (gb + 2 < 64) issue_b(sb, gb + 2, tid);

        if (bc == 0) {
            #pragma unroll
            for (int mf = 0; mf < 4; mf++)
                #pragma unroll
                for (int nf = 0; nf < 8; nf++)
                    #pragma unroll
                    for (int q = 0; q < 4; q++) acc[mf][nf][q] = 0.f;
        }

        uint32_t bBase = sb + BOFF + (gb % 3) * BSTG;
        int npass = (bc < 4) ? 2 : 1;

        #pragma unroll
        for (int ks = 0; ks < 4; ks++) {
            // B fragments: 64 cols, loaded ONCE, reused across A-limb passes
            uint32_t bfr[8][2];
            #pragma unroll
            for (int np = 0; np < 4; np++) {
                int code = nwarp * 64 + np * 16 + (l & 7) + ((l & 16) ? 8 : 0);
                int colb = ks * 32 + ((l & 8) ? 16 : 0);
                int off = code * 128 + colb;
                uint32_t r[4];
                LDMATRIX4(r, bBase + (off ^ ((off >> 3) & 0x70)));
                bfr[np * 2][0] = r[0]; bfr[np * 2][1] = r[1];
                bfr[np * 2 + 1][0] = r[2]; bfr[np * 2 + 1][1] = r[3];
            }
            for (int ps = 0; ps < npass; ps++) {
                int slab = (bc < 4) ? ((ps == 0) ? bc : bc + 4) : (bc - 4);
                uint32_t aBase = sb + slab * 16384;
                uint32_t afr[4][4];
                #pragma unroll
                for (int mf = 0; mf < 4; mf++) {
                    int row = mwarp * 64 + mf * 16 + (l & 15);
                    int colb = ks * 32 + ((l >> 4) << 4);
                    int off = row * 128 + colb;
                    LDMATRIX4(afr[mf], aBase + (off ^ ((off >> 3) & 0x70)));
                }
                #pragma unroll
                for (int mf = 0; mf < 4; mf++)
                    #pragma unroll
                    for (int nf = 0; nf < 8; nf++)
                        MMA16816(acc[mf][nf], afr[mf], bfr[nf]);
            }
        }

        if (bc == 7) {     // tile done: fused argmin epilogue (cols ascending)
            #pragma unroll
            for (int nf = 0; nf < 8; nf++) {
                int n0 = c0 + nwarp * 64 + nf * 8 + 2 * (l & 3);
                float nr0 = __ldg(&g_norms[n0]) * 4096.0f;
                float nr1 = __ldg(&g_norms[n0 + 1]) * 4096.0f;
                #pragma unroll
                for (int mf = 0; mf < 4; mf++) {
                    float d00 = fmaf(-2.0f, acc[mf][nf][0], nr0);
                    float d01 = fmaf(-2.0f, acc[mf][nf][1], nr1);
                    float d10 = fmaf(-2.0f, acc[mf][nf][2], nr0);
                    float d11 = fmaf(-2.0f, acc[mf][nf][3], nr1);
                    if (d00 < best[mf][0]) { best[mf][0] = d00; bidx[mf][0] = n0; }
                    if (d01 < best[mf][0]) { best[mf][0] = d01; bidx[mf][0] = n0 + 1; }
                    if (d10 < best[mf][1]) { best[mf][1] = d10; bidx[mf][1] = n0; }
                    if (d11 < best[mf][1]) { best[mf][1] = d11; bidx[mf][1] = n0 + 1; }
                }
            }
        }
    }

    // merge the 4 column-lanes (l&3), then packed atomicMin per row
    #pragma unroll
    for (int mf = 0; mf < 4; mf++)
        #pragma unroll
        for (int rh = 0; rh < 2; rh++) {
            float bv = best[mf][rh]; int bi = bidx[mf][rh];
            #pragma unroll
            for (int dlt = 1; dlt <= 2; dlt <<= 1) {
                float ov = __shfl_xor_sync(0xFFFFFFFFu, bv, dlt);
                int   oi = __shfl_xor_sync(0xFFFFFFFFu, bi, dlt);
                if (ov < bv || (ov == bv && oi < bi)) { bv = ov; bi = oi; }
            }
            if ((l & 3) == 0) {
                int row = mwarp * 64 + mf * 16 + rh * 8 + (l >> 2);
                uint32_t b = __float_as_uint(bv);
                b = (b & 0x80000000u) ? ~b : (b | 0x80000000u);   // monotone key
                unsigned long long key = ((unsigned long long)b << 32) | (uint32_t)bi;
                atomicMin(&sMin[row], key);
            }
        }
    __syncthreads();
    if (tid < 128) {
        int bi = (int)(uint32_t)(sMin[tid] & 0xFFFFFFFFULL);
        g_idx[row0 + tid] = bi;
        atomicAdd(&g_counts[bi], 1);
    }
}

// ---------------- epilogue kernels ----------------
__global__ __launch_bounds__(256) void quantize_kernel(const float* __restrict__ X,
                                                       float* __restrict__ out) {
    const int total4 = N_ROWS * D / 4;
    int stride = gridDim.x * blockDim.x;
    float sum = 0.f;
    for (int i = blockIdx.x * blockDim.x + threadIdx.x; i < total4; i += stride) {
        int row = i >> 6, d4 = (i & 63) << 2;
        float4 xv = ((const float4*)X)[i];
        float4 q = *(const float4*)&g_codeT[(size_t)g_idx[row] * D + d4];
        ((float4*)out)[i] = q;
        float dx = xv.x - q.x, dy = xv.y - q.y, dz = xv.z - q.z, dw = xv.w - q.w;
        sum += dx * dx + dy * dy + dz * dz + dw * dw;
    }
    __shared__ float s[256];
    s[threadIdx.x] = sum;
    __syncthreads();
    for (int r = 128; r > 0; r >>= 1) { if (threadIdx.x < r) s[threadIdx.x] += s[threadIdx.x + r]; __syncthreads(); }
    if (threadIdx.x == 0) g_partials[blockIdx.x] = s[0];
}

__global__ void finalize_kernel(float* __restrict__ out) {
    __shared__ double sd[256];
    int t = threadIdx.x;
    double s = 0.0;
    for (int i = t; i < 2048; i += 256) s += (double)g_partials[i];
    sd[t] = s;
    __syncthreads();
    for (int r = 128; r > 0; r >>= 1) { if (t < r) sd[t] += sd[t + r]; __syncthreads(); }
    double loss = 1.25 * sd[0] / (double)((long long)N_ROWS * D);
    __syncthreads();
    double h = 0.0;
    for (int i = t; i < K; i += 256) {
        double p = (double)g_counts[i] / (double)N_ROWS;
        h += p * log(p + 1e-10);
    }
    sd[t] = h;
    __syncthreads();
    for (int r = 128; r > 0; r >>= 1) { if (t < r) sd[t] += sd[t + r]; __syncthreads(); }
    if (t == 0) {
        out[(size_t)N_ROWS * D]     = (float)loss;
        out[(size_t)N_ROWS * D + 1] = (float)exp(-sd[0]);
    }
}

// ------------------------------------------------------------------
extern "C" void kernel_launch(void* const* d_in, const int* in_sizes, int n_in,
                              void* d_out, int out_size) {
    const float* x  = (const float*)d_in[0];
    const float* cb = (const float*)d_in[1];
    float* out = (float*)d_out;

    cudaFuncSetAttribute(argmin_mma_kernel,
                         cudaFuncAttributeMaxDynamicSharedMemorySize, SMEMSZ);

    transpose_kernel<<<dim3(K / 32, D / 32), dim3(32, 8)>>>(cb);
    norms_kernel<<<K, 256>>>();
    split_x_kernel<<<N_ROWS * D / 8 / 256, 256>>>(x);
    argmin_mma_kernel<<<N_ROWS / 128, 256, SMEMSZ>>>();
    quantize_kernel<<<2048, 256>>>(x, out);
    finalize_kernel<<<1, 256>>>(out);
}